// round 1
// baseline (speedup 1.0000x reference)
#include <cuda_runtime.h>
#include <math.h>

#define NN 100000
#define CC 16
#define GG 2
#define LL 2
#define EE 3200000
#define FF 512
#define HH 64

#define NBLK 98          // ceil(NN/1024)
#define EB   12500       // EE/256
#define PB   12500       // NN warps / 8 warps-per-block
#define FB   6250        // NN*CC/256

// ---------------- scratch (device globals: allocation-free) ----------------
__device__ int   g_cnt[NN];
__device__ int   g_tmpscan[NN];
__device__ int   g_rowptr[NN + 1];
__device__ int   g_wp[NN];
__device__ int   g_blksum[128];
__device__ int   g_blkoff[128];
__device__ int   g_ssrc[EE];
__device__ float g_sw0[EE];
__device__ float g_sw1[EE];
__device__ float g_h_tmp[NN * CC];
__device__ float g_hgA[NN * CC];
__device__ float g_hgB[NN * CC];
__device__ float g_hidden[NN * HH];

// ---------------- f32x2 helpers (packed fp32 FMA, sm_103a) -----------------
__device__ __forceinline__ unsigned long long pk2(float lo, float hi) {
    unsigned long long r;
    asm("mov.b64 %0, {%1, %2};" : "=l"(r) : "f"(lo), "f"(hi));
    return r;
}
__device__ __forceinline__ void upk2(unsigned long long v, float& lo, float& hi) {
    asm("mov.b64 {%0, %1}, %2;" : "=f"(lo), "=f"(hi) : "l"(v));
}
__device__ __forceinline__ void fma2(unsigned long long& d,
                                     unsigned long long a, unsigned long long b) {
    asm("fma.rn.f32x2 %0, %1, %2, %0;" : "+l"(d) : "l"(a), "l"(b));
}

// ---------------- CSR build ----------------
__global__ void zero_cnt_kernel() {
    int i = blockIdx.x * blockDim.x + threadIdx.x;
    if (i < NN) g_cnt[i] = 0;
}

__global__ void hist_kernel(const int* __restrict__ dst, const int* __restrict__ train) {
    int i = blockIdx.x * blockDim.x + threadIdx.x;
    if (i >= EE) return;
    int d = dst[i];
    if (train[d] == 0) atomicAdd(&g_cnt[d], 1);
}

__global__ void scan1_kernel() {
    __shared__ int s[1024];
    int i = blockIdx.x * 1024 + threadIdx.x;
    int v = (i < NN) ? g_cnt[i] : 0;
    s[threadIdx.x] = v;
    __syncthreads();
    #pragma unroll
    for (int off = 1; off < 1024; off <<= 1) {
        int t = (threadIdx.x >= off) ? s[threadIdx.x - off] : 0;
        __syncthreads();
        s[threadIdx.x] += t;
        __syncthreads();
    }
    if (i < NN) g_tmpscan[i] = s[threadIdx.x];
    if (threadIdx.x == 1023) g_blksum[blockIdx.x] = s[1023];
}

__global__ void scan2_kernel() {
    if (threadIdx.x == 0 && blockIdx.x == 0) {
        int run = 0;
        for (int b = 0; b < NBLK; b++) {
            g_blkoff[b] = run;
            run += g_blksum[b];
        }
    }
}

__global__ void scan3_kernel() {
    int i = blockIdx.x * 1024 + threadIdx.x;
    if (i < NN) {
        int incl = g_tmpscan[i] + g_blkoff[blockIdx.x];
        g_rowptr[i + 1] = incl;
        g_wp[i] = incl - g_cnt[i];
    }
    if (i == 0) g_rowptr[0] = 0;
}

__global__ void scatter_kernel(const int* __restrict__ src, const int* __restrict__ dst,
                               const float* __restrict__ e0, const float* __restrict__ e1,
                               const int* __restrict__ train) {
    int i = blockIdx.x * blockDim.x + threadIdx.x;
    if (i >= EE) return;
    int d = dst[i];
    if (train[d]) return;
    int p = atomicAdd(&g_wp[d], 1);
    g_ssrc[p] = src[i];
    g_sw0[p] = expf(e0[i]);   // softmax max-shift cancels; exp(|e|<6) is safe
    g_sw1[p] = expf(e1[i]);
}

// ---------------- propagate (gather, warp-per-node, 4 lanes/edge) ----------
__global__ __launch_bounds__(256) void prop_kernel(const float* __restrict__ label_init,
                                                   const int* __restrict__ train,
                                                   const float* __restrict__ one_hot,
                                                   int layer, int out_sel) {
    int n    = (blockIdx.x * blockDim.x + threadIdx.x) >> 5;
    int lane = threadIdx.x & 31;
    if (n >= NN) return;

    const float* h_in  = (layer == 0) ? label_init : g_h_tmp;
    const float* swp   = (layer == 0) ? g_sw0 : g_sw1;
    float*       h_out = (out_sel == 0) ? g_h_tmp : ((out_sel == 1) ? g_hgA : g_hgB);

    if (train[n]) {
        if (lane < CC) h_out[(size_t)n * CC + lane] = one_hot[(size_t)n * CC + lane];
        return;
    }

    int beg = g_rowptr[n], end = g_rowptr[n + 1];
    int q = lane & 3;                      // class quad this lane owns
    float4 acc = make_float4(0.f, 0.f, 0.f, 0.f);
    float sw_sum = 0.f;

    for (int j = beg + (lane >> 2); j < end; j += 8) {
        int   s = g_ssrc[j];
        float w = swp[j];
        float4 hv = *(const float4*)(h_in + (size_t)s * CC + q * 4);
        acc.x = fmaf(w, hv.x, acc.x);
        acc.y = fmaf(w, hv.y, acc.y);
        acc.z = fmaf(w, hv.z, acc.z);
        acc.w = fmaf(w, hv.w, acc.w);
        sw_sum += w;
    }
    // butterfly over edge-slots only (xor 4,8,16): same-q lanes combine
    #pragma unroll
    for (int off = 4; off < 32; off <<= 1) {
        acc.x  += __shfl_xor_sync(0xFFFFFFFFu, acc.x,  off);
        acc.y  += __shfl_xor_sync(0xFFFFFFFFu, acc.y,  off);
        acc.z  += __shfl_xor_sync(0xFFFFFFFFu, acc.z,  off);
        acc.w  += __shfl_xor_sync(0xFFFFFFFFu, acc.w,  off);
        sw_sum += __shfl_xor_sync(0xFFFFFFFFu, sw_sum, off);
    }
    if (lane < 4) {
        float inv = (sw_sum > 0.f) ? (1.f / sw_sum) : 0.f;
        float4 o = make_float4(acc.x * inv, acc.y * inv, acc.z * inv, acc.w * inv);
        *(float4*)(h_out + (size_t)n * CC + q * 4) = o;
    }
}

// ---------------- MLP layer 1: X[N,512]@W1[512,64]+b1, relu ----------------
__global__ __launch_bounds__(256) void gemm1_kernel(const float* __restrict__ X,
                                                    const float* __restrict__ W,
                                                    const float* __restrict__ B) {
    __shared__ __align__(16) float Xs[16][132];
    __shared__ __align__(16) float Ws[16][64];
    int tid = threadIdx.x;
    int tn = tid & 31;    // node group: nodes tn*4 .. tn*4+3
    int th = tid >> 5;    // h group:    h th*8 .. th*8+7
    int n0 = blockIdx.x * 128;

    unsigned long long acc[4][4];
    #pragma unroll
    for (int i = 0; i < 4; i++)
        #pragma unroll
        for (int j = 0; j < 4; j++) acc[i][j] = 0ull;

    for (int k0 = 0; k0 < FF; k0 += 16) {
        #pragma unroll
        for (int r = 0; r < 2; r++) {
            int v = tid + r * 256;
            int node = v >> 2, kq = v & 3;
            int gn = n0 + node;
            float4 xv = make_float4(0.f, 0.f, 0.f, 0.f);
            if (gn < NN) xv = *(const float4*)(X + (size_t)gn * FF + k0 + kq * 4);
            Xs[kq * 4 + 0][node] = xv.x;
            Xs[kq * 4 + 1][node] = xv.y;
            Xs[kq * 4 + 2][node] = xv.z;
            Xs[kq * 4 + 3][node] = xv.w;
        }
        {
            int kk = tid >> 4, hq = tid & 15;
            *(float4*)&Ws[kk][hq * 4] = *(const float4*)(W + (size_t)(k0 + kk) * HH + hq * 4);
        }
        __syncthreads();
        #pragma unroll
        for (int kk = 0; kk < 16; kk++) {
            float4 xv = *(const float4*)&Xs[kk][tn * 4];
            float4 wa = *(const float4*)&Ws[kk][th * 8];
            float4 wb = *(const float4*)&Ws[kk][th * 8 + 4];
            unsigned long long xp[4], wq[4];
            xp[0] = pk2(xv.x, xv.x); xp[1] = pk2(xv.y, xv.y);
            xp[2] = pk2(xv.z, xv.z); xp[3] = pk2(xv.w, xv.w);
            wq[0] = pk2(wa.x, wa.y); wq[1] = pk2(wa.z, wa.w);
            wq[2] = pk2(wb.x, wb.y); wq[3] = pk2(wb.z, wb.w);
            #pragma unroll
            for (int i = 0; i < 4; i++)
                #pragma unroll
                for (int j = 0; j < 4; j++) fma2(acc[i][j], xp[i], wq[j]);
        }
        __syncthreads();
    }

    float bb[8];
    #pragma unroll
    for (int j = 0; j < 8; j++) bb[j] = B[th * 8 + j];
    #pragma unroll
    for (int i = 0; i < 4; i++) {
        int gn = n0 + tn * 4 + i;
        if (gn >= NN) continue;
        float o[8];
        #pragma unroll
        for (int j = 0; j < 4; j++) {
            float lo, hi;
            upk2(acc[i][j], lo, hi);
            o[2 * j] = lo; o[2 * j + 1] = hi;
        }
        #pragma unroll
        for (int j = 0; j < 8; j++) o[j] = fmaxf(o[j] + bb[j], 0.f);
        float4* dp = (float4*)(g_hidden + (size_t)gn * HH + th * 8);
        dp[0] = make_float4(o[0], o[1], o[2], o[3]);
        dp[1] = make_float4(o[4], o[5], o[6], o[7]);
    }
}

// ---------------- MLP layer 2 + attention combine + output ------------------
__global__ __launch_bounds__(256) void final_kernel(const float* __restrict__ w2,
                                                    const float* __restrict__ b2,
                                                    const float* __restrict__ att,
                                                    const float* __restrict__ alpha,
                                                    float* __restrict__ out) {
    __shared__ float sw2[HH * CC];
    for (int i = threadIdx.x; i < HH * CC; i += blockDim.x) sw2[i] = w2[i];
    __syncthreads();
    int idx = blockIdx.x * blockDim.x + threadIdx.x;
    if (idx >= NN * CC) return;
    int n = idx >> 4, c = idx & 15;

    float m = b2[c];
    const float4* hr = (const float4*)(g_hidden + (size_t)n * HH);
    #pragma unroll
    for (int k = 0; k < 16; k++) {
        float4 hv = hr[k];
        m = fmaf(hv.x, sw2[(4 * k + 0) * CC + c], m);
        m = fmaf(hv.y, sw2[(4 * k + 1) * CC + c], m);
        m = fmaf(hv.z, sw2[(4 * k + 2) * CC + c], m);
        m = fmaf(hv.w, sw2[(4 * k + 3) * CC + c], m);
    }

    float a0 = att[n * 2 + 0], a1 = att[n * 2 + 1];
    float mx = fmaxf(a0, a1);
    float e0 = expf(a0 - mx), e1 = expf(a1 - mx);
    float inv = 1.f / (e0 + e1);
    float at0 = e0 * inv, at1 = e1 * inv;

    float sa = 1.f / (1.f + expf(-alpha[n]));
    float logits = g_hgA[idx] * at0 + g_hgB[idx] * at1;
    out[idx] = sa * logits + (1.f - sa) * m;
}

// ---------------- launcher ----------------
extern "C" void kernel_launch(void* const* d_in, const int* in_sizes, int n_in,
                              void* d_out, int out_size) {
    (void)in_sizes; (void)n_in; (void)out_size;
    const float* features   = (const float*)d_in[0];
    const float* label_init = (const float*)d_in[1];
    const float* one_hot    = (const float*)d_in[2];
    const float* alpha      = (const float*)d_in[3];
    const float* attention  = (const float*)d_in[4];
    const float* e_edge     = (const float*)d_in[5];
    const float* w1         = (const float*)d_in[6];
    const float* b1         = (const float*)d_in[7];
    const float* w2         = (const float*)d_in[8];
    const float* b2         = (const float*)d_in[9];
    const int*   src        = (const int*)d_in[10];
    const int*   dst        = (const int*)d_in[11];
    const int*   train      = (const int*)d_in[12];
    float*       out        = (float*)d_out;

    // MLP layer 1 (independent of graph part)
    gemm1_kernel<<<(NN + 127) / 128, 256>>>(features, w1, b1);

    for (int g = 0; g < GG; g++) {
        const int*   dst_g = dst + (size_t)g * EE;
        const int*   src_g = src + (size_t)g * EE;
        const float* e0    = e_edge + (size_t)(0 * GG + g) * EE;
        const float* e1    = e_edge + (size_t)(1 * GG + g) * EE;

        zero_cnt_kernel<<<(NN + 255) / 256, 256>>>();
        hist_kernel<<<EB, 256>>>(dst_g, train);
        scan1_kernel<<<NBLK, 1024>>>();
        scan2_kernel<<<1, 32>>>();
        scan3_kernel<<<NBLK, 1024>>>();
        scatter_kernel<<<EB, 256>>>(src_g, dst_g, e0, e1, train);

        // layer 0: label_init -> g_h_tmp ; layer 1: g_h_tmp -> g_hgA/g_hgB
        prop_kernel<<<PB, 256>>>(label_init, train, one_hot, 0, 0);
        prop_kernel<<<PB, 256>>>(label_init, train, one_hot, 1, (g == 0) ? 1 : 2);
    }

    final_kernel<<<FB, 256>>>(w2, b2, attention, alpha, out);
}

// round 2
// speedup vs baseline: 1.1548x; 1.1548x over previous
#include <cuda_runtime.h>
#include <math.h>

#define NN 100000
#define CC 16
#define EE 3200000
#define FF 512
#define HH 64
#define VN (2*NN)

#define NBLK2 196        // ceil(VN/1024)
#define EB2   25000      // 2*EE/256
#define PB2   25000      // VN warps / 8 warps-per-block
#define FB    6250       // NN*CC/256

// ---------------- scratch (device globals: allocation-free) ----------------
__device__ int    g_cnt[VN];
__device__ int    g_tmpscan[VN];
__device__ int    g_rowptr[VN + 1];
__device__ int    g_wp[VN];
__device__ int    g_blksum[256];
__device__ int    g_blkoff[256];
__device__ float4 g_edge[2 * EE];         // (src, expf(e_l0), expf(e_l1), pad)
__device__ float  g_h0[VN * CC];          // layer-0 output, both graphs
__device__ float  g_hg[VN * CC];          // layer-1 output, both graphs
__device__ float  g_hidden[NN * HH];
__device__ float  g_w1t[FF * HH];         // tf32-rounded W1

// ---------------- tf32 mma helpers ----------------
__device__ __forceinline__ unsigned f2tf32(float x) {
    unsigned r;
    asm("cvt.rna.tf32.f32 %0, %1;" : "=r"(r) : "f"(x));
    return r;
}
__device__ __forceinline__ void mma_tf32(float c[4], const unsigned a[4], const unsigned b[2]) {
    asm volatile("mma.sync.aligned.m16n8k8.row.col.f32.tf32.tf32.f32 "
                 "{%0,%1,%2,%3}, {%4,%5,%6,%7}, {%8,%9}, {%0,%1,%2,%3};"
                 : "+f"(c[0]), "+f"(c[1]), "+f"(c[2]), "+f"(c[3])
                 : "r"(a[0]), "r"(a[1]), "r"(a[2]), "r"(a[3]), "r"(b[0]), "r"(b[1]));
}

// ---------------- W1 tf32 pre-truncation ----------------
__global__ void w1_trunc_kernel(const float* __restrict__ w1) {
    int i = blockIdx.x * blockDim.x + threadIdx.x;
    if (i < FF * HH) g_w1t[i] = __uint_as_float(f2tf32(w1[i]));
}

// ---------------- MLP layer 1 via tensor cores --------------------------
// X[N,512] @ W1t[512,64] + b1, relu. Warp tile m32n64; block 8 warps = m256.
__global__ __launch_bounds__(256) void gemm1_tc(const float* __restrict__ X,
                                                const float* __restrict__ bias) {
    int warp = threadIdx.x >> 5, lane = threadIdx.x & 31;
    int gid = lane >> 2, tig = lane & 3;
    int wbase = blockIdx.x * 256 + warp * 32;

    float acc[2][8][4];
    #pragma unroll
    for (int mt = 0; mt < 2; mt++)
        #pragma unroll
        for (int nt = 0; nt < 8; nt++)
            #pragma unroll
            for (int r = 0; r < 4; r++) acc[mt][nt][r] = 0.f;

    for (int k0 = 0; k0 < FF; k0 += 8) {
        unsigned bf[8][2];
        #pragma unroll
        for (int nt = 0; nt < 8; nt++) {
            bf[nt][0] = __float_as_uint(g_w1t[(k0 + tig) * HH + nt * 8 + gid]);
            bf[nt][1] = __float_as_uint(g_w1t[(k0 + tig + 4) * HH + nt * 8 + gid]);
        }
        unsigned af[2][4];
        #pragma unroll
        for (int mt = 0; mt < 2; mt++) {
            int r0 = wbase + mt * 16 + gid;
            int r1 = r0 + 8;
            float x0 = (r0 < NN) ? X[(size_t)r0 * FF + k0 + tig] : 0.f;
            float x1 = (r1 < NN) ? X[(size_t)r1 * FF + k0 + tig] : 0.f;
            float x2 = (r0 < NN) ? X[(size_t)r0 * FF + k0 + tig + 4] : 0.f;
            float x3 = (r1 < NN) ? X[(size_t)r1 * FF + k0 + tig + 4] : 0.f;
            af[mt][0] = f2tf32(x0); af[mt][1] = f2tf32(x1);
            af[mt][2] = f2tf32(x2); af[mt][3] = f2tf32(x3);
        }
        #pragma unroll
        for (int mt = 0; mt < 2; mt++)
            #pragma unroll
            for (int nt = 0; nt < 8; nt++)
                mma_tf32(acc[mt][nt], af[mt], bf[nt]);
    }

    #pragma unroll
    for (int mt = 0; mt < 2; mt++) {
        #pragma unroll
        for (int rr = 0; rr < 2; rr++) {
            int row = wbase + mt * 16 + rr * 8 + gid;
            if (row >= NN) continue;
            #pragma unroll
            for (int nt = 0; nt < 8; nt++) {
                int col = nt * 8 + 2 * tig;
                float v0 = fmaxf(acc[mt][nt][rr * 2 + 0] + bias[col], 0.f);
                float v1 = fmaxf(acc[mt][nt][rr * 2 + 1] + bias[col + 1], 0.f);
                *(float2*)(g_hidden + (size_t)row * HH + col) = make_float2(v0, v1);
            }
        }
    }
}

// ---------------- CSR build (both graphs fused; virtual node = g*NN + n) ----
__global__ void zero_cnt_kernel() {
    int i = blockIdx.x * blockDim.x + threadIdx.x;
    if (i < VN) g_cnt[i] = 0;
}

__global__ void hist_kernel(const int* __restrict__ dst, const int* __restrict__ train) {
    int i = blockIdx.x * blockDim.x + threadIdx.x;
    if (i >= 2 * EE) return;
    int d = dst[i];
    if (train[d] == 0) {
        int base = (i >= EE) ? NN : 0;
        atomicAdd(&g_cnt[base + d], 1);
    }
}

__global__ void scan1_kernel() {
    __shared__ int s[1024];
    int i = blockIdx.x * 1024 + threadIdx.x;
    int v = (i < VN) ? g_cnt[i] : 0;
    s[threadIdx.x] = v;
    __syncthreads();
    #pragma unroll
    for (int off = 1; off < 1024; off <<= 1) {
        int t = (threadIdx.x >= off) ? s[threadIdx.x - off] : 0;
        __syncthreads();
        s[threadIdx.x] += t;
        __syncthreads();
    }
    if (i < VN) g_tmpscan[i] = s[threadIdx.x];
    if (threadIdx.x == 1023) g_blksum[blockIdx.x] = s[1023];
}

__global__ void scan2_kernel() {
    __shared__ int s[256];
    int t = threadIdx.x;
    int v = (t < NBLK2) ? g_blksum[t] : 0;
    s[t] = v;
    __syncthreads();
    #pragma unroll
    for (int off = 1; off < 256; off <<= 1) {
        int u = (t >= off) ? s[t - off] : 0;
        __syncthreads();
        s[t] += u;
        __syncthreads();
    }
    if (t < NBLK2) g_blkoff[t] = s[t] - v;   // exclusive
}

__global__ void scan3_kernel() {
    int i = blockIdx.x * 1024 + threadIdx.x;
    if (i < VN) {
        int incl = g_tmpscan[i] + g_blkoff[blockIdx.x];
        g_rowptr[i + 1] = incl;
        g_wp[i] = incl - g_cnt[i];
    }
    if (i == 0) g_rowptr[0] = 0;
}

__global__ void scatter_kernel(const int* __restrict__ src, const int* __restrict__ dst,
                               const float* __restrict__ e_edge, const int* __restrict__ train) {
    int i = blockIdx.x * blockDim.x + threadIdx.x;
    if (i >= 2 * EE) return;
    int d = dst[i];
    if (train[d]) return;
    int base = (i >= EE) ? NN : 0;
    int p = atomicAdd(&g_wp[base + d], 1);
    // softmax max-shift cancels; exp(|e|<6) safe. e layout [L,G,E]: l0 -> i, l1 -> 2E+i.
    g_edge[p] = make_float4(__int_as_float(src[i]), __expf(e_edge[i]), __expf(e_edge[2 * EE + i]), 0.f);
}

// ---------------- propagate (gather, warp-per-vnode, 4 lanes/edge) ----------
template <int LAYER>
__global__ __launch_bounds__(256) void prop_kernel(const float* __restrict__ label_init,
                                                   const int* __restrict__ train,
                                                   const float* __restrict__ one_hot) {
    int v    = (blockIdx.x * blockDim.x + threadIdx.x) >> 5;
    int lane = threadIdx.x & 31;
    if (v >= VN) return;
    int n = (v < NN) ? v : v - NN;

    float* out = ((LAYER == 0) ? g_h0 : g_hg) + (size_t)v * CC;
    if (train[n]) {
        if (lane < CC) out[lane] = one_hot[(size_t)n * CC + lane];
        return;
    }

    const float* hin = (LAYER == 0) ? label_init
                                    : (g_h0 + ((v < NN) ? (size_t)0 : (size_t)NN * CC));
    int beg = g_rowptr[v], end = g_rowptr[v + 1];
    int q = lane & 3;
    float4 acc = make_float4(0.f, 0.f, 0.f, 0.f);
    float sw_sum = 0.f;

    for (int j = beg + (lane >> 2); j < end; j += 8) {
        float4 ed = g_edge[j];
        int   s = __float_as_int(ed.x);
        float w = (LAYER == 0) ? ed.y : ed.z;
        float4 hv = *(const float4*)(hin + (size_t)s * CC + q * 4);
        acc.x = fmaf(w, hv.x, acc.x);
        acc.y = fmaf(w, hv.y, acc.y);
        acc.z = fmaf(w, hv.z, acc.z);
        acc.w = fmaf(w, hv.w, acc.w);
        sw_sum += w;
    }
    #pragma unroll
    for (int off = 4; off < 32; off <<= 1) {
        acc.x  += __shfl_xor_sync(0xFFFFFFFFu, acc.x,  off);
        acc.y  += __shfl_xor_sync(0xFFFFFFFFu, acc.y,  off);
        acc.z  += __shfl_xor_sync(0xFFFFFFFFu, acc.z,  off);
        acc.w  += __shfl_xor_sync(0xFFFFFFFFu, acc.w,  off);
        sw_sum += __shfl_xor_sync(0xFFFFFFFFu, sw_sum, off);
    }
    if (lane < 4) {
        float inv = (sw_sum > 0.f) ? (1.f / sw_sum) : 0.f;
        *(float4*)(out + q * 4) = make_float4(acc.x * inv, acc.y * inv, acc.z * inv, acc.w * inv);
    }
}

// ---------------- MLP layer 2 + attention combine + output ------------------
__global__ __launch_bounds__(256) void final_kernel(const float* __restrict__ w2,
                                                    const float* __restrict__ b2,
                                                    const float* __restrict__ att,
                                                    const float* __restrict__ alpha,
                                                    float* __restrict__ out) {
    __shared__ float sw2[HH * CC];
    for (int i = threadIdx.x; i < HH * CC; i += blockDim.x) sw2[i] = w2[i];
    __syncthreads();
    int idx = blockIdx.x * blockDim.x + threadIdx.x;
    if (idx >= NN * CC) return;
    int n = idx >> 4, c = idx & 15;

    float m = b2[c];
    const float4* hr = (const float4*)(g_hidden + (size_t)n * HH);
    #pragma unroll
    for (int k = 0; k < 16; k++) {
        float4 hv = hr[k];
        m = fmaf(hv.x, sw2[(4 * k + 0) * CC + c], m);
        m = fmaf(hv.y, sw2[(4 * k + 1) * CC + c], m);
        m = fmaf(hv.z, sw2[(4 * k + 2) * CC + c], m);
        m = fmaf(hv.w, sw2[(4 * k + 3) * CC + c], m);
    }

    float a0 = att[n * 2 + 0], a1 = att[n * 2 + 1];
    float mx = fmaxf(a0, a1);
    float e0 = expf(a0 - mx), e1 = expf(a1 - mx);
    float inv = 1.f / (e0 + e1);

    float sa = 1.f / (1.f + expf(-alpha[n]));
    float logits = g_hg[idx] * (e0 * inv) + g_hg[(size_t)(NN + n) * CC + c] * (e1 * inv);
    out[idx] = sa * logits + (1.f - sa) * m;
}

// ---------------- launcher ----------------
extern "C" void kernel_launch(void* const* d_in, const int* in_sizes, int n_in,
                              void* d_out, int out_size) {
    (void)in_sizes; (void)n_in; (void)out_size;
    const float* features   = (const float*)d_in[0];
    const float* label_init = (const float*)d_in[1];
    const float* one_hot    = (const float*)d_in[2];
    const float* alpha      = (const float*)d_in[3];
    const float* attention  = (const float*)d_in[4];
    const float* e_edge     = (const float*)d_in[5];
    const float* w1         = (const float*)d_in[6];
    const float* b1         = (const float*)d_in[7];
    const float* w2         = (const float*)d_in[8];
    const float* b2         = (const float*)d_in[9];
    const int*   src        = (const int*)d_in[10];
    const int*   dst        = (const int*)d_in[11];
    const int*   train      = (const int*)d_in[12];
    float*       out        = (float*)d_out;

    // MLP layer 1 (tensor cores)
    w1_trunc_kernel<<<(FF * HH + 255) / 256, 256>>>(w1);
    gemm1_tc<<<(NN + 255) / 256, 256>>>(features, b1);

    // fused CSR build for both graphs
    zero_cnt_kernel<<<(VN + 255) / 256, 256>>>();
    hist_kernel<<<EB2, 256>>>(dst, train);
    scan1_kernel<<<NBLK2, 1024>>>();
    scan2_kernel<<<1, 256>>>();
    scan3_kernel<<<NBLK2, 1024>>>();
    scatter_kernel<<<EB2, 256>>>(src, dst, e_edge, train);

    // propagation, both graphs per launch
    prop_kernel<0><<<PB2, 256>>>(label_init, train, one_hot);
    prop_kernel<1><<<PB2, 256>>>(label_init, train, one_hot);

    final_kernel<<<FB, 256>>>(w2, b2, attention, alpha, out);
}

// round 3
// speedup vs baseline: 1.4506x; 1.2561x over previous
#include <cuda_runtime.h>
#include <math.h>

#define NN 100000
#define CC 16
#define EE 3200000
#define FF 512
#define HH 64
#define VN (2*NN)

#define NBLK2 196        // ceil(VN/1024)
#define EB4   6250       // 2*EE/(256*4)
#define PB2   25000      // VN warps / 8 warps-per-block
#define FB    6250       // NN*CC/256
#define GEMM_BLKS 782    // ceil(NN/128)
#define MASKW 3125       // NN/32

// ---------------- scratch (device globals: allocation-free) ----------------
__device__ int      g_cnt[VN];
__device__ int      g_tmpscan[VN];
__device__ int      g_rowptr[VN + 1];
__device__ int      g_wp[VN];
__device__ int      g_blksum[256];
__device__ int      g_blkoff[256];
__device__ unsigned g_trainbit[MASKW];
__device__ float4   g_edge[2 * EE];       // (src, expf(e_l0), expf(e_l1), pad)
__device__ float    g_h0[VN * CC];        // layer-0 output, both graphs
__device__ float    g_hg[VN * CC];        // layer-1 output, both graphs
__device__ float    g_hidden[NN * HH];
__device__ float    g_w1t[FF * HH];       // tf32-rounded W1

// ---------------- tf32 mma helpers ----------------
__device__ __forceinline__ unsigned f2tf32(float x) {
    unsigned r;
    asm("cvt.rna.tf32.f32 %0, %1;" : "=r"(r) : "f"(x));
    return r;
}
__device__ __forceinline__ void mma_tf32(float c[4], const unsigned a[4], const unsigned b[2]) {
    asm volatile("mma.sync.aligned.m16n8k8.row.col.f32.tf32.tf32.f32 "
                 "{%0,%1,%2,%3}, {%4,%5,%6,%7}, {%8,%9}, {%0,%1,%2,%3};"
                 : "+f"(c[0]), "+f"(c[1]), "+f"(c[2]), "+f"(c[3])
                 : "r"(a[0]), "r"(a[1]), "r"(a[2]), "r"(a[3]), "r"(b[0]), "r"(b[1]));
}
__device__ __forceinline__ bool is_train(int d) {
    return (g_trainbit[d >> 5] >> (d & 31)) & 1u;
}

// ---------------- prep: train bitmask + W1 tf32 truncation ------------------
__global__ void prep_kernel(const int* __restrict__ train, const float* __restrict__ w1) {
    int i = blockIdx.x * blockDim.x + threadIdx.x;
    if (i < FF * HH) g_w1t[i] = __uint_as_float(f2tf32(w1[i]));
    if (i < MASKW) {
        unsigned m = 0;
        #pragma unroll 8
        for (int b = 0; b < 32; b++)
            m |= (train[i * 32 + b] != 0 ? 1u : 0u) << b;
        g_trainbit[i] = m;
    }
}

// ---------------- hist (bitmask + int4 vectorized) --------------------------
__global__ __launch_bounds__(256) void hist_kernel(const int* __restrict__ dst) {
    int t = blockIdx.x * 256 + threadIdx.x;          // t < 1.6M, covers 4 edges
    int4 d4 = ((const int4*)dst)[t];
    int base = ((t << 2) >= EE) ? NN : 0;            // EE % 4 == 0: no straddle
    if (!is_train(d4.x)) atomicAdd(&g_cnt[base + d4.x], 1);
    if (!is_train(d4.y)) atomicAdd(&g_cnt[base + d4.y], 1);
    if (!is_train(d4.z)) atomicAdd(&g_cnt[base + d4.z], 1);
    if (!is_train(d4.w)) atomicAdd(&g_cnt[base + d4.w], 1);
}

// ---------------- scan ----------------
__global__ void scan1_kernel() {
    __shared__ int s[1024];
    int i = blockIdx.x * 1024 + threadIdx.x;
    int v = (i < VN) ? g_cnt[i] : 0;
    s[threadIdx.x] = v;
    __syncthreads();
    #pragma unroll
    for (int off = 1; off < 1024; off <<= 1) {
        int t = (threadIdx.x >= off) ? s[threadIdx.x - off] : 0;
        __syncthreads();
        s[threadIdx.x] += t;
        __syncthreads();
    }
    if (i < VN) g_tmpscan[i] = s[threadIdx.x];
    if (threadIdx.x == 1023) g_blksum[blockIdx.x] = s[1023];
}

__global__ void scan2_kernel() {
    __shared__ int s[256];
    int t = threadIdx.x;
    int v = (t < NBLK2) ? g_blksum[t] : 0;
    s[t] = v;
    __syncthreads();
    #pragma unroll
    for (int off = 1; off < 256; off <<= 1) {
        int u = (t >= off) ? s[t - off] : 0;
        __syncthreads();
        s[t] += u;
        __syncthreads();
    }
    if (t < NBLK2) g_blkoff[t] = s[t] - v;   // exclusive
}

__global__ void scan3_kernel() {
    int i = blockIdx.x * 1024 + threadIdx.x;
    if (i < VN) {
        int incl = g_tmpscan[i] + g_blkoff[blockIdx.x];
        g_rowptr[i + 1] = incl;
        g_wp[i] = incl - g_cnt[i];
    }
    if (i == 0) g_rowptr[0] = 0;
}

// ---------------- fused: tf32 GEMM (blocks < GEMM_BLKS) + edge scatter ------
// GEMM: X[N,512] @ W1t[512,64] + b1, relu -> g_hidden. Block tile m128n64,
// 8 warps each m16n64, smem-staged, conflict-free padded.
__global__ __launch_bounds__(256) void scatter_gemm_kernel(
        const int* __restrict__ src, const int* __restrict__ dst,
        const float* __restrict__ e_edge,
        const float* __restrict__ X, const float* __restrict__ bias) {
    __shared__ float Xs[16][136];   // [k][row], pad 8: conflict-free frag loads
    __shared__ float Ws[16][72];    // [k][n],  pad 8

    if (blockIdx.x < GEMM_BLKS) {
        int tid = threadIdx.x;
        int warp = tid >> 5, lane = tid & 31;
        int gid = lane >> 2, tig = lane & 3;
        int m0 = warp * 16;
        int n0 = blockIdx.x * 128;

        float acc[8][4];
        #pragma unroll
        for (int nt = 0; nt < 8; nt++)
            #pragma unroll
            for (int r = 0; r < 4; r++) acc[nt][r] = 0.f;

        for (int k0 = 0; k0 < FF; k0 += 16) {
            // stage X tile (128 rows x 16 k) as [k][row]
            #pragma unroll
            for (int r = 0; r < 2; r++) {
                int v = tid + r * 256;
                int row = v >> 2, kq = v & 3;
                int gn = n0 + row;
                float4 xv = make_float4(0.f, 0.f, 0.f, 0.f);
                if (gn < NN) xv = *(const float4*)(X + (size_t)gn * FF + k0 + kq * 4);
                Xs[kq * 4 + 0][row] = xv.x;
                Xs[kq * 4 + 1][row] = xv.y;
                Xs[kq * 4 + 2][row] = xv.z;
                Xs[kq * 4 + 3][row] = xv.w;
            }
            // stage W tile (16 k x 64 n), already tf32
            {
                int kk = tid >> 4, nq = tid & 15;
                float4 wv = *(const float4*)(g_w1t + (size_t)(k0 + kk) * HH + nq * 4);
                Ws[kk][nq * 4 + 0] = wv.x;
                Ws[kk][nq * 4 + 1] = wv.y;
                Ws[kk][nq * 4 + 2] = wv.z;
                Ws[kk][nq * 4 + 3] = wv.w;
            }
            __syncthreads();
            #pragma unroll
            for (int ks = 0; ks < 2; ks++) {
                unsigned a[4];
                a[0] = f2tf32(Xs[ks * 8 + tig    ][m0 + gid    ]);
                a[1] = f2tf32(Xs[ks * 8 + tig    ][m0 + gid + 8]);
                a[2] = f2tf32(Xs[ks * 8 + tig + 4][m0 + gid    ]);
                a[3] = f2tf32(Xs[ks * 8 + tig + 4][m0 + gid + 8]);
                #pragma unroll
                for (int nt = 0; nt < 8; nt++) {
                    unsigned b[2];
                    b[0] = __float_as_uint(Ws[ks * 8 + tig    ][nt * 8 + gid]);
                    b[1] = __float_as_uint(Ws[ks * 8 + tig + 4][nt * 8 + gid]);
                    mma_tf32(acc[nt], a, b);
                }
            }
            __syncthreads();
        }
        // epilogue: bias + relu
        #pragma unroll
        for (int rr = 0; rr < 2; rr++) {
            int row = n0 + m0 + rr * 8 + gid;
            if (row >= NN) continue;
            #pragma unroll
            for (int nt = 0; nt < 8; nt++) {
                int col = nt * 8 + 2 * tig;
                float v0 = fmaxf(acc[nt][rr * 2 + 0] + bias[col], 0.f);
                float v1 = fmaxf(acc[nt][rr * 2 + 1] + bias[col + 1], 0.f);
                *(float2*)(g_hidden + (size_t)row * HH + col) = make_float2(v0, v1);
            }
        }
        return;
    }

    // ---- scatter branch (bitmask + x4 vectorized) ----
    int t = (blockIdx.x - GEMM_BLKS) * 256 + threadIdx.x;   // covers 4 edges
    int4   s4 = ((const int4*)src)[t];
    int4   d4 = ((const int4*)dst)[t];
    float4 e0 = ((const float4*)e_edge)[t];
    float4 e1 = ((const float4*)(e_edge + 2 * (size_t)EE))[t];
    int base = ((t << 2) >= EE) ? NN : 0;
    // softmax max-shift cancels; exp(|e|<6) safe
    if (!is_train(d4.x)) {
        int p = atomicAdd(&g_wp[base + d4.x], 1);
        g_edge[p] = make_float4(__int_as_float(s4.x), __expf(e0.x), __expf(e1.x), 0.f);
    }
    if (!is_train(d4.y)) {
        int p = atomicAdd(&g_wp[base + d4.y], 1);
        g_edge[p] = make_float4(__int_as_float(s4.y), __expf(e0.y), __expf(e1.y), 0.f);
    }
    if (!is_train(d4.z)) {
        int p = atomicAdd(&g_wp[base + d4.z], 1);
        g_edge[p] = make_float4(__int_as_float(s4.z), __expf(e0.z), __expf(e1.z), 0.f);
    }
    if (!is_train(d4.w)) {
        int p = atomicAdd(&g_wp[base + d4.w], 1);
        g_edge[p] = make_float4(__int_as_float(s4.w), __expf(e0.w), __expf(e1.w), 0.f);
    }
}

// ---------------- propagate (gather, warp-per-vnode, 4 lanes/edge) ----------
template <int LAYER>
__global__ __launch_bounds__(256) void prop_kernel(const float* __restrict__ label_init,
                                                   const float* __restrict__ one_hot) {
    int v    = (blockIdx.x * blockDim.x + threadIdx.x) >> 5;
    int lane = threadIdx.x & 31;
    if (v >= VN) return;
    int n = (v < NN) ? v : v - NN;

    float* out = ((LAYER == 0) ? g_h0 : g_hg) + (size_t)v * CC;
    if (is_train(n)) {
        if (lane < CC) out[lane] = one_hot[(size_t)n * CC + lane];
        return;
    }

    const float* hin = (LAYER == 0) ? label_init
                                    : (g_h0 + ((v < NN) ? (size_t)0 : (size_t)NN * CC));
    int beg = g_rowptr[v], end = g_rowptr[v + 1];
    int q = lane & 3;
    float4 acc = make_float4(0.f, 0.f, 0.f, 0.f);
    float sw_sum = 0.f;

    for (int j = beg + (lane >> 2); j < end; j += 8) {
        float4 ed = g_edge[j];
        int   s = __float_as_int(ed.x);
        float w = (LAYER == 0) ? ed.y : ed.z;
        float4 hv = *(const float4*)(hin + (size_t)s * CC + q * 4);
        acc.x = fmaf(w, hv.x, acc.x);
        acc.y = fmaf(w, hv.y, acc.y);
        acc.z = fmaf(w, hv.z, acc.z);
        acc.w = fmaf(w, hv.w, acc.w);
        sw_sum += w;
    }
    #pragma unroll
    for (int off = 4; off < 32; off <<= 1) {
        acc.x  += __shfl_xor_sync(0xFFFFFFFFu, acc.x,  off);
        acc.y  += __shfl_xor_sync(0xFFFFFFFFu, acc.y,  off);
        acc.z  += __shfl_xor_sync(0xFFFFFFFFu, acc.z,  off);
        acc.w  += __shfl_xor_sync(0xFFFFFFFFu, acc.w,  off);
        sw_sum += __shfl_xor_sync(0xFFFFFFFFu, sw_sum, off);
    }
    if (lane < 4) {
        float inv = (sw_sum > 0.f) ? (1.f / sw_sum) : 0.f;
        *(float4*)(out + q * 4) = make_float4(acc.x * inv, acc.y * inv, acc.z * inv, acc.w * inv);
    }
}

// ---------------- MLP layer 2 + attention combine + output ------------------
__global__ __launch_bounds__(256) void final_kernel(const float* __restrict__ w2,
                                                    const float* __restrict__ b2,
                                                    const float* __restrict__ att,
                                                    const float* __restrict__ alpha,
                                                    float* __restrict__ out) {
    __shared__ float sw2[HH * CC];
    for (int i = threadIdx.x; i < HH * CC; i += blockDim.x) sw2[i] = w2[i];
    __syncthreads();
    int idx = blockIdx.x * blockDim.x + threadIdx.x;
    if (idx >= NN * CC) return;
    int n = idx >> 4, c = idx & 15;

    float m = b2[c];
    const float4* hr = (const float4*)(g_hidden + (size_t)n * HH);
    #pragma unroll
    for (int k = 0; k < 16; k++) {
        float4 hv = hr[k];
        m = fmaf(hv.x, sw2[(4 * k + 0) * CC + c], m);
        m = fmaf(hv.y, sw2[(4 * k + 1) * CC + c], m);
        m = fmaf(hv.z, sw2[(4 * k + 2) * CC + c], m);
        m = fmaf(hv.w, sw2[(4 * k + 3) * CC + c], m);
    }

    float a0 = att[n * 2 + 0], a1 = att[n * 2 + 1];
    float mx = fmaxf(a0, a1);
    float e0 = expf(a0 - mx), e1 = expf(a1 - mx);
    float inv = 1.f / (e0 + e1);

    float sa = 1.f / (1.f + expf(-alpha[n]));
    float logits = g_hg[idx] * (e0 * inv) + g_hg[(size_t)(NN + n) * CC + c] * (e1 * inv);
    out[idx] = sa * logits + (1.f - sa) * m;
}

// ---------------- launcher ----------------
extern "C" void kernel_launch(void* const* d_in, const int* in_sizes, int n_in,
                              void* d_out, int out_size) {
    (void)in_sizes; (void)n_in; (void)out_size;
    const float* features   = (const float*)d_in[0];
    const float* label_init = (const float*)d_in[1];
    const float* one_hot    = (const float*)d_in[2];
    const float* alpha      = (const float*)d_in[3];
    const float* attention  = (const float*)d_in[4];
    const float* e_edge     = (const float*)d_in[5];
    const float* w1         = (const float*)d_in[6];
    const float* b1         = (const float*)d_in[7];
    const float* w2         = (const float*)d_in[8];
    const float* b2         = (const float*)d_in[9];
    const int*   src        = (const int*)d_in[10];
    const int*   dst        = (const int*)d_in[11];
    const int*   train      = (const int*)d_in[12];
    float*       out        = (float*)d_out;

    void* cnt_ptr = nullptr;
    cudaGetSymbolAddress(&cnt_ptr, g_cnt);
    cudaMemsetAsync(cnt_ptr, 0, VN * sizeof(int));

    prep_kernel<<<(FF * HH + 255) / 256, 256>>>(train, w1);
    hist_kernel<<<EB4, 256>>>(dst);
    scan1_kernel<<<NBLK2, 1024>>>();
    scan2_kernel<<<1, 256>>>();
    scan3_kernel<<<NBLK2, 1024>>>();

    // GEMM blocks first (long pole), then scatter blocks
    scatter_gemm_kernel<<<GEMM_BLKS + EB4, 256>>>(src, dst, e_edge, features, b1);

    prop_kernel<0><<<PB2, 256>>>(label_init, one_hot);
    prop_kernel<1><<<PB2, 256>>>(label_init, one_hot);

    final_kernel<<<FB, 256>>>(w2, b2, attention, alpha, out);
}